// round 15
// baseline (speedup 1.0000x reference)
#include <cuda_runtime.h>

// SmoothAPLoss via interleaved dual histogram + one-warp tail, single kernel.
// (Resubmission of R13/R14 source — prior two rounds died to broker infra
//  failures before measurement; R12 evidence still motivates NB 1024 -> 256.)
//   val = p - (is_pos ? DELTA : 0), b = clamp((int)(val*NB))
//   g_hist[b] = {ncnt, nsum, pcnt, psum}
//   total = sum_b [ pcnt[b]*ssum[b] - scnt[b]*psum[b] ]  (ssum/scnt = inclusive
//   suffix sums of negative histogram); npos = sum_b pcnt[b].
// Last block's warp 0 runs the whole tail with warp shuffles only (no barriers).
// All state self-cleans for graph replay. NB=256: quantization rel err ~1e-5,
// ~70x under the 1e-3 threshold.

#define DELTA 0.01f
#define NB    256
#define TPB   512
#define BPT   (NB / 32)      // 8 bins per tail-warp thread

__device__ __align__(16) float4 g_hist[NB];   // {ncnt, nsum, pcnt, psum}
__device__ int g_done;

__device__ __forceinline__ float warp_suffix_incl(float v, int lane) {
#pragma unroll
    for (int off = 1; off < 32; off <<= 1) {
        float o = __shfl_down_sync(0xFFFFFFFFu, v, off);
        if (lane + off < 32) v += o;
    }
    return v;
}

__global__ void __launch_bounds__(TPB)
fused_kernel(const float2* __restrict__ pred, const int* __restrict__ lab,
             int n, float* __restrict__ out) {
    const int tid = threadIdx.x;
    const int lane = tid & 31;

    // ---- phase 1: sigmoid + interleaved histogram (spread REDG atomics,
    //      count+sum adjacent in one 16B cell -> same L2 sector) ----
    int i = blockIdx.x * TPB + tid;
    if (i < n) {
        float2 x = pred[i];
        float p = __fdividef(1.0f, 1.0f + __expf(x.x - x.y));
        bool is_pos = (lab[i] == 1);
        float val = is_pos ? (p - DELTA) : p;
        int b = max(0, min((int)(val * (float)NB), NB - 1));
        float* cell = (float*)&g_hist[b] + (is_pos ? 2 : 0);
        atomicAdd(cell, 1.0f);        // count
        atomicAdd(cell + 1, val);     // sum
    }

    // ---- done-counter: last block runs the tail ----
    __threadfence();
    __syncthreads();
    __shared__ int s_last;
    if (tid == 0)
        s_last = (atomicAdd(&g_done, 1) == (int)gridDim.x - 1) ? 1 : 0;
    __syncthreads();
    if (!s_last || tid >= 32) return;

    // ---- tail: ONE WARP, shuffle-only (no barriers) ----
    const int base = lane * BPT;
    float4 h[BPT];
#pragma unroll
    for (int j = 0; j < BPT; j++)
        h[j] = __ldcg(&g_hist[base + j]);

    // self-clean for next graph replay
    float4 z = make_float4(0.f, 0.f, 0.f, 0.f);
#pragma unroll
    for (int j = 0; j < BPT; j++)
        g_hist[base + j] = z;
    if (lane == 0) g_done = 0;

    // thread totals
    float ct = 0.f, st = 0.f, pt = 0.f;
#pragma unroll
    for (int j = 0; j < BPT; j++) { ct += h[j].x; st += h[j].y; pt += h[j].z; }

    // inclusive suffix scans across the 32 lanes (negative count / sum)
    float ic = warp_suffix_incl(ct, lane);
    float is = warp_suffix_incl(st, lane);
    float ip = warp_suffix_incl(pt, lane);    // lane 0 = npos

    // descending pass within thread: running inclusive suffix + dot terms
    float runc = ic - ct;
    float runs = is - st;
    float a = 0.0f;
#pragma unroll
    for (int j = BPT - 1; j >= 0; j--) {
        runc += h[j].x;
        runs += h[j].y;
        a += h[j].z * runs - runc * h[j].w;
    }

    // warp reduce the dot partials
#pragma unroll
    for (int off = 16; off > 0; off >>= 1)
        a += __shfl_down_sync(0xFFFFFFFFu, a, off);

    if (lane == 0) {
        float npos = fmaxf(ip, 1.0f);
        out[0] = (float)((double)a / (double)npos);
    }
}

extern "C" void kernel_launch(void* const* d_in, const int* in_sizes, int n_in,
                              void* d_out, int out_size) {
    const float2* pred = (const float2*)d_in[0];
    const int* lab = (const int*)d_in[1];
    float* out = (float*)d_out;
    int n = in_sizes[1];

    int nblk = (n + TPB - 1) / TPB;   // 32 for N=16384
    fused_kernel<<<nblk, TPB>>>(pred, lab, n, out);
}

// round 16
// speedup vs baseline: 1.0623x; 1.0623x over previous
#include <cuda_runtime.h>

// SmoothAPLoss via dual histogram (NB=1024), block-local smem accumulation.
//   total = sum_b [ pcnt[b]*ssum[b] - scnt[b]*psum[b] ],  ssum/scnt = inclusive
//   suffix sums of the negative histogram; npos = sum_b pcnt[b].
// Phase 1 histograms into SMEM (ATOMS, ~zero contention), then a predicated
// REDG merge into global. NB=256 regression (R15) showed global same-address
// atomic contention at the p~0.5 peak is the binding cost; smem kills it.
// Last block runs R12's proven tail. All state self-cleans for graph replay.

#define DELTA 0.01f
#define NB    1024
#define TPB   512
#define ITEMS 2
#define BPT   (NB / TPB)     // 2 bins per thread in the tail

__device__ __align__(16) float g_ncnt[NB];
__device__ __align__(16) float g_nsum[NB];
__device__ __align__(16) float g_pcnt[NB];
__device__ __align__(16) float g_psum[NB];
__device__ int g_done;

__device__ __forceinline__ float warp_suffix_incl(float v, int lane) {
#pragma unroll
    for (int off = 1; off < 32; off <<= 1) {
        float o = __shfl_down_sync(0xFFFFFFFFu, v, off);
        if (lane + off < 32) v += o;
    }
    return v;
}

__global__ void __launch_bounds__(TPB)
fused_kernel(const float2* __restrict__ pred, const int* __restrict__ lab,
             int n, float* __restrict__ out) {
    __shared__ float4 sh[NB];        // {ncnt, nsum, pcnt, psum} per bin
    const int tid = threadIdx.x;
    const int lane = tid & 31;
    const int wid = tid >> 5;

    // zero block-local histogram
#pragma unroll
    for (int j = tid; j < NB; j += TPB)
        sh[j] = make_float4(0.f, 0.f, 0.f, 0.f);
    __syncthreads();

    // ---- phase 1: sigmoid + smem histogram (ATOMS, ~zero contention) ----
    const int base_i = blockIdx.x * (TPB * ITEMS);
#pragma unroll
    for (int k = 0; k < ITEMS; k++) {
        int i = base_i + k * TPB + tid;
        if (i < n) {
            float2 x = pred[i];
            float p = __fdividef(1.0f, 1.0f + __expf(x.x - x.y));
            bool is_pos = (lab[i] == 1);
            float val = is_pos ? (p - DELTA) : p;
            int b = max(0, min((int)(val * (float)NB), NB - 1));
            float* cell = (float*)&sh[b] + (is_pos ? 2 : 0);
            atomicAdd(cell, 1.0f);
            atomicAdd(cell + 1, val);
        }
    }
    __syncthreads();

    // ---- merge: predicated REDG, only touched cells ----
#pragma unroll
    for (int j = tid; j < NB; j += TPB) {
        float4 h = sh[j];
        if (h.x != 0.0f) {
            atomicAdd(&g_ncnt[j], h.x);
            atomicAdd(&g_nsum[j], h.y);
        }
        if (h.z != 0.0f) {
            atomicAdd(&g_pcnt[j], h.z);
            atomicAdd(&g_psum[j], h.w);
        }
    }

    // ---- done-counter: last block runs the tail ----
    __threadfence();
    __syncthreads();
    __shared__ int s_last;
    if (tid == 0)
        s_last = (atomicAdd(&g_done, 1) == (int)gridDim.x - 1) ? 1 : 0;
    __syncthreads();
    if (!s_last) return;

    // ---- tail (R12 structure): scan + dot product over NB bins ----
    __shared__ float wtc[32], wts[32], wtp[32];
    __shared__ double wred[TPB / 32];
    __shared__ float s_npos;

    const int base = tid * BPT;

    float2 a2 = __ldcg((const float2*)&g_ncnt[base]);
    float2 b2 = __ldcg((const float2*)&g_nsum[base]);
    float2 c2 = __ldcg((const float2*)&g_pcnt[base]);
    float2 d2 = __ldcg((const float2*)&g_psum[base]);
    float nc[BPT] = {a2.x, a2.y};
    float ns[BPT] = {b2.x, b2.y};
    float pc[BPT] = {c2.x, c2.y};
    float ps[BPT] = {d2.x, d2.y};

    // self-clean for next graph replay
    float2 z2 = make_float2(0.f, 0.f);
    *(float2*)&g_ncnt[base] = z2;
    *(float2*)&g_nsum[base] = z2;
    *(float2*)&g_pcnt[base] = z2;
    *(float2*)&g_psum[base] = z2;

    float ct = nc[0] + nc[1];
    float st = ns[0] + ns[1];
    float pt = pc[0] + pc[1];

    float ic = warp_suffix_incl(ct, lane);
    float is = warp_suffix_incl(st, lane);
    float ip = warp_suffix_incl(pt, lane);
    if (lane == 0) { wtc[wid] = ic; wts[wid] = is; wtp[wid] = ip; }
    __syncthreads();

    if (wid == 0) {
        float cc = (lane < TPB / 32) ? wtc[lane] : 0.0f;
        float ss = (lane < TPB / 32) ? wts[lane] : 0.0f;
        float pp = (lane < TPB / 32) ? wtp[lane] : 0.0f;
        float cci = warp_suffix_incl(cc, lane);
        float ssi = warp_suffix_incl(ss, lane);
        float ppi = warp_suffix_incl(pp, lane);
        if (lane < TPB / 32) { wtc[lane] = cci - cc; wts[lane] = ssi - ss; }
        if (lane == 0) s_npos = ppi;
    }
    if (tid == 0) g_done = 0;
    __syncthreads();

    float runc = (ic - ct) + wtc[wid];
    float runs = (is - st) + wts[wid];
    float a = 0.0f;
#pragma unroll
    for (int j = BPT - 1; j >= 0; j--) {
        runc += nc[j];
        runs += ns[j];
        a += pc[j] * runs - runc * ps[j];
    }

    for (int off = 16; off > 0; off >>= 1)
        a += __shfl_down_sync(0xFFFFFFFFu, a, off);
    if (lane == 0) wred[wid] = (double)a;
    __syncthreads();
    if (tid == 0) {
        double t = 0.0;
#pragma unroll
        for (int w = 0; w < TPB / 32; w++) t += wred[w];
        double denom = (double)fmaxf(s_npos, 1.0f);
        out[0] = (float)(t / denom);
    }
}

extern "C" void kernel_launch(void* const* d_in, const int* in_sizes, int n_in,
                              void* d_out, int out_size) {
    const float2* pred = (const float2*)d_in[0];
    const int* lab = (const int*)d_in[1];
    float* out = (float*)d_out;
    int n = in_sizes[1];

    int nblk = (n + TPB * ITEMS - 1) / (TPB * ITEMS);   // 16 for N=16384
    fused_kernel<<<nblk, TPB>>>(pred, lab, n, out);
}